// round 9
// baseline (speedup 1.0000x reference)
#include <cuda_runtime.h>
#include <cuda_bf16.h>
#include <cstdint>

#define NBLK   128
#define NTHR   256
#define SEQ    1024
#define TLEN   256
#define HID    512
#define NSTEPS (SEQ + TLEN)
#define NGRP   8       // batch groups
#define NHT    16      // hidden tiles per group
#define BTILE  32      // batches per CTA
#define HTILE  32      // hidden units per CTA
#define NC     128     // gate columns per CTA (4 gates x 32 hidden)
#define PITCH  520     // bf16 elems per SMEM row: 1040B, %128B = 16B -> LDSM conflict-free
#define GS     132     // gates_s row stride (floats)

__device__ unsigned g_bar_count;
__device__ unsigned g_bar_gen;
__device__ unsigned g_flags[NGRP][NHT][32];  // [group][htile][128B pad]
__device__ __nv_bfloat16 g_h[2][256][HID];   // ping-pong hidden state (bf16)

__device__ __forceinline__ float tanh_fast(float x) {
    float y;
    asm("tanh.approx.f32 %0, %1;" : "=f"(y) : "f"(x));
    return y;
}
__device__ __forceinline__ float sigm(float x) {
    return fmaf(tanh_fast(0.5f * x), 0.5f, 0.5f);
}

// One-time device-wide barrier (init only). 128 CTAs, 1/SM => co-resident.
__device__ __forceinline__ void gridbar() {
    __syncthreads();
    if (threadIdx.x == 0) {
        unsigned target = *(volatile unsigned*)&g_bar_gen;
        unsigned arr;
        asm volatile("atom.acq_rel.gpu.global.add.u32 %0, [%1], 1;"
                     : "=r"(arr) : "l"(&g_bar_count) : "memory");
        if (arr == NBLK - 1) {
            asm volatile("st.relaxed.gpu.global.u32 [%0], %1;"
                         :: "l"(&g_bar_count), "r"(0u) : "memory");
            asm volatile("red.release.gpu.global.add.u32 [%0], %1;"
                         :: "l"(&g_bar_gen), "r"(1u) : "memory");
        } else {
            unsigned g;
            do {
                __nanosleep(20);
                asm volatile("ld.acquire.gpu.global.u32 %0, [%1];"
                             : "=r"(g) : "l"(&g_bar_gen) : "memory");
            } while (g == target);
        }
    }
    __syncthreads();
}

__device__ __forceinline__ void load_w(const float* __restrict__ Whh,
                                       const float* __restrict__ bih,
                                       const float* __restrict__ bhh,
                                       const float* __restrict__ Wih,
                                       __nv_bfloat16* W_s, float* bias_s, float* wih_s,
                                       int h_base, int tid) {
    // SMEM gate-col n = g*32 + jj  <->  global gate row g*512 + h_base + jj
    for (int idx = tid; idx < NC * HID; idx += NTHR) {
        int n = idx >> 9;
        int k = idx & (HID - 1);
        int grow = (n >> 5) * HID + h_base + (n & 31);
        W_s[n * PITCH + k] = __float2bfloat16_rn(Whh[grow * HID + k]);
    }
    if (tid < NC) {
        int grow = (tid >> 5) * HID + h_base + (tid & 31);
        bias_s[tid] = bih[grow] + bhh[grow];
        wih_s[tid]  = Wih[grow];
    }
}

#define LDSM_X4(R, addr)                                                      \
    asm volatile("ldmatrix.sync.aligned.m8n8.x4.shared.b16 {%0,%1,%2,%3}, [%4];" \
                 : "=r"((R)[0]), "=r"((R)[1]), "=r"((R)[2]), "=r"((R)[3])     \
                 : "r"(addr))

#define MMA_BF16(C, A, B0, B1)                                                \
    asm volatile(                                                             \
        "mma.sync.aligned.m16n8k16.row.col.f32.bf16.bf16.f32 "                \
        "{%0,%1,%2,%3}, {%4,%5,%6,%7}, {%8,%9}, {%0,%1,%2,%3};"               \
        : "+f"((C)[0]), "+f"((C)[1]), "+f"((C)[2]), "+f"((C)[3])              \
        : "r"((A)[0]), "r"((A)[1]), "r"((A)[2]), "r"((A)[3]), "r"(B0), "r"(B1))

// Wait for the 4 producer htiles of chunk CH to have completed step s-1.
#define GATE(CH) do {                                                         \
    const unsigned* fp = &g_flags[bg][(CH) * 4 + (lane & 3)][0];              \
    unsigned v;                                                               \
    while (true) {                                                            \
        asm volatile("ld.acquire.gpu.global.u32 %0, [%1];"                    \
                     : "=r"(v) : "l"(fp) : "memory");                         \
        if (v >= (unsigned)s) break;                                          \
        __nanosleep(25);                                                      \
    }                                                                         \
} while (0)

// Issue chunk CH loads: 32 rows x 128 bf16 cols = 8KB = 512 x 16B, 2 per thread.
#define ISSUE(CH) do {                                                        \
    _Pragma("unroll")                                                         \
    for (int o = 0; o < 2; ++o) {                                             \
        int idx = o * 256 + tid;                                              \
        int row = idx >> 4;                                                   \
        int k   = (CH) * 128 + (idx & 15) * 8;                                \
        const __nv_bfloat16* gp = hsrc + (b_base + row) * HID + k;            \
        unsigned sdst = a_u32 + (unsigned)(row * PITCH + k) * 2u;             \
        asm volatile("cp.async.cg.shared.global [%0], [%1], 16;"              \
                     :: "r"(sdst), "l"(gp));                                  \
    }                                                                         \
    asm volatile("cp.async.commit_group;");                                   \
} while (0)

#define COMP(CH) do {                                                         \
    _Pragma("unroll")                                                         \
    for (int ki = 0; ki < 8; ++ki) {                                          \
        const unsigned kkb = (unsigned)((CH) * 128 + ki * 16) * 2u;           \
        unsigned a0[4], a1[4];                                                \
        LDSM_X4(a0, aAddr0 + kkb);                                            \
        LDSM_X4(a1, aAddr1 + kkb);                                            \
        const int bi = ((CH) * 8 + ki) * 4;                                   \
        MMA_BF16(C[0][0], a0, bfrag[bi + 0], bfrag[bi + 1]);                  \
        MMA_BF16(C[0][1], a0, bfrag[bi + 2], bfrag[bi + 3]);                  \
        MMA_BF16(C[1][0], a1, bfrag[bi + 0], bfrag[bi + 1]);                  \
        MMA_BF16(C[1][1], a1, bfrag[bi + 2], bfrag[bi + 3]);                  \
    }                                                                         \
} while (0)

__global__ void __launch_bounds__(NTHR, 1)
lstm_seq2seq_kernel(const float* __restrict__ inputs,
                    const float* __restrict__ eWih, const float* __restrict__ eWhh,
                    const float* __restrict__ ebih, const float* __restrict__ ebhh,
                    const float* __restrict__ dWih, const float* __restrict__ dWhh,
                    const float* __restrict__ dbih, const float* __restrict__ dbhh,
                    const float* __restrict__ linW, const float* __restrict__ linb,
                    float* __restrict__ out) {
    extern __shared__ char smraw[];
    __nv_bfloat16* W_s = (__nv_bfloat16*)smraw;        // 128 x 520 bf16
    __nv_bfloat16* A_s = W_s + NC * PITCH;             // 32 x 520 bf16
    float* G_s    = (float*)(A_s + BTILE * PITCH);     // 32 x 132 f32
    float* bias_s = G_s + BTILE * GS;                  // 128
    float* wih_s  = bias_s + NC;                       // 128
    float* x_s    = wih_s + NC;                        // 32

    const int tid    = threadIdx.x;
    const int bx     = blockIdx.x;
    const int bg     = bx & 7;             // 8 batch groups of 16 CTAs
    const int b_base = bg * BTILE;
    const int htile  = bx >> 3;            // 16 hidden tiles
    const int h_base = htile * HTILE;
    const int lane   = tid & 31;
    const int warp   = tid >> 5;           // warp tile: 32(m) x 16(n), n = warp*16
    const int jj     = tid & 31;           // hidden-within-tile (== lane)
    const int bq     = tid >> 5;           // batch quad base

    // ldmatrix lane addresses
    const unsigned a_u32 = (unsigned)__cvta_generic_to_shared(A_s);
    const unsigned w_u32 = (unsigned)__cvta_generic_to_shared(W_s);
    const int lg = lane >> 3, lr = lane & 7;
    const unsigned aAddr0 = a_u32 + (unsigned)(((lg & 1) * 8 + lr) * PITCH + (lg >> 1) * 8) * 2u;
    const unsigned aAddr1 = aAddr0 + 16u * PITCH * 2u;
    const unsigned bAddr  = w_u32 + (unsigned)((warp * 16 + (lg >> 1) * 8 + lr) * PITCH + (lg & 1) * 8) * 2u;

    // Init: zero g_h[0], d_out, own flag
    {
        unsigned* h0 = (unsigned*)&g_h[0][0][0];
        for (int i = tid; i < 512; i += NTHR) h0[bx * 512 + i] = 0u;
        for (int i = tid; i < 512; i += NTHR) out[bx * 512 + i] = 0.0f;
        if (tid == 0) g_flags[bg][htile][0] = 0u;
    }
    load_w(eWhh, ebih, ebhh, eWih, W_s, bias_s, wih_s, h_base, tid);

    const float lw  = linW[h_base + jj];
    const float lb0 = linb[0];
    float creg[4];
    #pragma unroll
    for (int i = 0; i < 4; ++i) creg[i] = 0.0f;

    gridbar();   // flags reset + h/out zero + W_s visible

    // B fragments resident in registers (rebuilt at decoder switch)
    unsigned bfrag[128];
    #pragma unroll
    for (int ki = 0; ki < 32; ++ki)
        LDSM_X4(&bfrag[ki * 4], bAddr + (unsigned)(ki * 32));

    for (int s = 0; s < NSTEPS; ++s) {
        const int  cur = s & 1;
        const int  nxt = cur ^ 1;
        const bool dec = (s >= SEQ);

        if (s == SEQ) {                    // switch to decoder weights
            __syncthreads();               // everyone done reading bias_s/wih_s
            load_w(dWhh, dbih, dbhh, dWih, W_s, bias_s, wih_s, h_base, tid);
            __syncthreads();
            #pragma unroll
            for (int ki = 0; ki < 32; ++ki)
                LDSM_X4(&bfrag[ki * 4], bAddr + (unsigned)(ki * 32));
        }

        const __nv_bfloat16* hsrc = &g_h[cur][0][0];

        float C[2][2][4];
        #pragma unroll
        for (int t = 0; t < 2; ++t)
            #pragma unroll
            for (int u = 0; u < 2; ++u)
                #pragma unroll
                for (int r = 0; r < 4; ++r) C[t][u][r] = 0.0f;

        GATE(0); ISSUE(0);
        GATE(1); ISSUE(1);
        asm volatile("cp.async.wait_group 1;");
        __syncthreads();
        COMP(0);
        GATE(2); ISSUE(2);
        asm volatile("cp.async.wait_group 1;");
        __syncthreads();
        COMP(1);
        GATE(3); ISSUE(3);
        asm volatile("cp.async.wait_group 1;");
        __syncthreads();
        COMP(2);
        asm volatile("cp.async.wait_group 0;");
        __syncthreads();
        COMP(3);

        // x feedback (all 16 producer flags >= s observed by now)
        if (tid < BTILE) {
            float xv;
            if (!dec)          xv = inputs[(b_base + tid) * SEQ + s];
            else if (s == SEQ) xv = inputs[(b_base + tid) * SEQ + (SEQ - 1)];
            else               xv = __ldcg(&out[(b_base + tid) * TLEN + (s - SEQ - 1)]);
            x_s[tid] = xv;
        }

        // C frags -> gates SMEM
        #pragma unroll
        for (int t = 0; t < 2; ++t) {
            const int r = t * 16 + (lane >> 2);
            #pragma unroll
            for (int u = 0; u < 2; ++u) {
                const int cc = warp * 16 + u * 8 + (lane & 3) * 2;
                *(float2*)&G_s[r * GS + cc]       = make_float2(C[t][u][0], C[t][u][1]);
                *(float2*)&G_s[(r + 8) * GS + cc] = make_float2(C[t][u][2], C[t][u][3]);
            }
        }
        __syncthreads();

        // Epilogue: 4 cells/thread, cell (b, jj); c in registers
        #pragma unroll
        for (int ci = 0; ci < 4; ++ci) {
            const int   b  = bq + ci * 8;
            const float xv = x_s[b];
            const float* gr = G_s + b * GS;
            const float gi = gr[jj]      + bias_s[jj]      + xv * wih_s[jj];
            const float gf = gr[32 + jj] + bias_s[32 + jj] + xv * wih_s[32 + jj];
            const float gg = gr[64 + jj] + bias_s[64 + jj] + xv * wih_s[64 + jj];
            const float go = gr[96 + jj] + bias_s[96 + jj] + xv * wih_s[96 + jj];
            const float cn = sigm(gf) * creg[ci] + sigm(gi) * tanh_fast(gg);
            creg[ci] = cn;
            const float h = sigm(go) * tanh_fast(cn);
            g_h[nxt][b_base + b][h_base + jj] = __float2bfloat16_rn(h);
            if (dec) {
                float p = h * lw;
                #pragma unroll
                for (int off = 16; off; off >>= 1)
                    p += __shfl_xor_sync(0xffffffffu, p, off);
                if (lane == 0) {
                    if (htile == 0) p += lb0;
                    atomicAdd(&out[(b_base + b) * TLEN + (s - SEQ)], p);
                }
            }
        }

        // Publish: all threads' h stores (and atomics) done -> release flag
        __syncthreads();
        if (tid == 0)
            asm volatile("st.release.gpu.global.u32 [%0], %1;"
                         :: "l"(&g_flags[bg][htile][0]), "r"((unsigned)(s + 1)) : "memory");
    }
}

extern "C" void kernel_launch(void* const* d_in, const int* in_sizes, int n_in,
                              void* d_out, int out_size) {
    const float* inputs = (const float*)d_in[0];
    const float* eWih   = (const float*)d_in[1];
    const float* eWhh   = (const float*)d_in[2];
    const float* ebih   = (const float*)d_in[3];
    const float* ebhh   = (const float*)d_in[4];
    const float* dWih   = (const float*)d_in[5];
    const float* dWhh   = (const float*)d_in[6];
    const float* dbih   = (const float*)d_in[7];
    const float* dbhh   = (const float*)d_in[8];
    const float* linW   = (const float*)d_in[9];
    const float* linb   = (const float*)d_in[10];
    float* out = (float*)d_out;

    const int smem = (NC * PITCH + BTILE * PITCH) * 2                 // bf16 W + A
                   + (BTILE * GS + 2 * NC + BTILE) * 4;               // f32 G + bias/wih/x
    cudaFuncSetAttribute(lstm_seq2seq_kernel,
                         cudaFuncAttributeMaxDynamicSharedMemorySize, smem);
    lstm_seq2seq_kernel<<<NBLK, NTHR, smem>>>(inputs, eWih, eWhh, ebih, ebhh,
                                              dWih, dWhh, dbih, dbhh, linW, linb, out);
}

// round 13
// speedup vs baseline: 1.2974x; 1.2974x over previous
#include <cuda_runtime.h>
#include <cuda_bf16.h>
#include <cstdint>

#define NBLK   128
#define NTHR   256
#define SEQ    1024
#define TLEN   256
#define HID    512
#define NSTEPS (SEQ + TLEN)
#define NGRP   8       // batch groups
#define NHT    16      // hidden tiles per group
#define BTILE  32      // batches per CTA
#define HTILE  32      // hidden units per CTA
#define NC     128     // gate columns per CTA (4 gates x 32 hidden)
#define PITCH  520     // bf16 elems per SMEM row: 1040B -> LDSM conflict-free
#define GS     132     // gates_s row stride (floats)

__device__ unsigned g_bar_count;
__device__ unsigned g_bar_gen;
__device__ unsigned g_flags[NGRP][NHT][32];  // [group][htile][128B pad]
__device__ __nv_bfloat16 g_h[2][256][HID];   // ping-pong hidden state (bf16)

__device__ __forceinline__ float tanh_fast(float x) {
    float y;
    asm("tanh.approx.f32 %0, %1;" : "=f"(y) : "f"(x));
    return y;
}
__device__ __forceinline__ float sigm(float x) {
    return fmaf(tanh_fast(0.5f * x), 0.5f, 0.5f);
}

// One-time device-wide barrier (init only). 128 CTAs, 1/SM => co-resident.
__device__ __forceinline__ void gridbar() {
    __syncthreads();
    if (threadIdx.x == 0) {
        unsigned target = *(volatile unsigned*)&g_bar_gen;
        unsigned arr;
        asm volatile("atom.acq_rel.gpu.global.add.u32 %0, [%1], 1;"
                     : "=r"(arr) : "l"(&g_bar_count) : "memory");
        if (arr == NBLK - 1) {
            asm volatile("st.relaxed.gpu.global.u32 [%0], %1;"
                         :: "l"(&g_bar_count), "r"(0u) : "memory");
            asm volatile("red.release.gpu.global.add.u32 [%0], %1;"
                         :: "l"(&g_bar_gen), "r"(1u) : "memory");
        } else {
            unsigned g;
            do {
                __nanosleep(20);
                asm volatile("ld.acquire.gpu.global.u32 %0, [%1];"
                             : "=r"(g) : "l"(&g_bar_gen) : "memory");
            } while (g == target);
        }
    }
    __syncthreads();
}

__device__ __forceinline__ void load_w(const float* __restrict__ Whh,
                                       const float* __restrict__ bih,
                                       const float* __restrict__ bhh,
                                       const float* __restrict__ Wih,
                                       __nv_bfloat16* W_s, float* bias_s, float* wih_s,
                                       int h_base, int tid) {
    // SMEM gate-col n = g*32 + jj  <->  global gate row g*512 + h_base + jj
    for (int idx = tid; idx < NC * HID; idx += NTHR) {
        int n = idx >> 9;
        int k = idx & (HID - 1);
        int grow = (n >> 5) * HID + h_base + (n & 31);
        W_s[n * PITCH + k] = __float2bfloat16_rn(Whh[grow * HID + k]);
    }
    if (tid < NC) {
        int grow = (tid >> 5) * HID + h_base + (tid & 31);
        bias_s[tid] = bih[grow] + bhh[grow];
        wih_s[tid]  = Wih[grow];
    }
}

#define LDSM_X4(R, addr)                                                      \
    asm volatile("ldmatrix.sync.aligned.m8n8.x4.shared.b16 {%0,%1,%2,%3}, [%4];" \
                 : "=r"((R)[0]), "=r"((R)[1]), "=r"((R)[2]), "=r"((R)[3])     \
                 : "r"(addr))

#define MMA_BF16(C, A, B0, B1)                                                \
    asm volatile(                                                             \
        "mma.sync.aligned.m16n8k16.row.col.f32.bf16.bf16.f32 "                \
        "{%0,%1,%2,%3}, {%4,%5,%6,%7}, {%8,%9}, {%0,%1,%2,%3};"               \
        : "+f"((C)[0]), "+f"((C)[1]), "+f"((C)[2]), "+f"((C)[3])              \
        : "r"((A)[0]), "r"((A)[1]), "r"((A)[2]), "r"((A)[3]), "r"(B0), "r"(B1))

// Wait for the 4 producer htiles of chunk CH to have completed step s-1.
#define GATE(CH) do {                                                         \
    const unsigned* fp = &g_flags[bg][(CH) * 4 + (lane & 3)][0];              \
    unsigned v;                                                               \
    while (true) {                                                            \
        asm volatile("ld.acquire.gpu.global.u32 %0, [%1];"                    \
                     : "=r"(v) : "l"(fp) : "memory");                         \
        if (v >= (unsigned)s) break;                                          \
        __nanosleep(25);                                                      \
    }                                                                         \
} while (0)

// Issue chunk CH loads: 32 rows x 128 bf16 cols = 8KB = 512 x 16B, 2 per thread.
#define ISSUE(CH) do {                                                        \
    _Pragma("unroll")                                                         \
    for (int o = 0; o < 2; ++o) {                                             \
        int idx = o * 256 + tid;                                              \
        int row = idx >> 4;                                                   \
        int k   = (CH) * 128 + (idx & 15) * 8;                                \
        const __nv_bfloat16* gp = hsrc + (b_base + row) * HID + k;            \
        unsigned sdst = a_u32 + (unsigned)(row * PITCH + k) * 2u;             \
        asm volatile("cp.async.cg.shared.global [%0], [%1], 16;"              \
                     :: "r"(sdst), "l"(gp));                                  \
    }                                                                         \
    asm volatile("cp.async.commit_group;");                                   \
} while (0)

// Compute chunk CH: B frags via LDSM from SMEM (W resident), A frags via LDSM.
#define COMP(CH) do {                                                         \
    _Pragma("unroll")                                                         \
    for (int ki = 0; ki < 8; ++ki) {                                          \
        const unsigned kkb = (unsigned)((CH) * 128 + ki * 16) * 2u;           \
        unsigned a0[4], a1[4], bf[4];                                         \
        LDSM_X4(a0, aAddr0 + kkb);                                            \
        LDSM_X4(a1, aAddr1 + kkb);                                            \
        LDSM_X4(bf, bAddr + kkb);                                             \
        MMA_BF16(C[0][0], a0, bf[0], bf[1]);                                  \
        MMA_BF16(C[0][1], a0, bf[2], bf[3]);                                  \
        MMA_BF16(C[1][0], a1, bf[0], bf[1]);                                  \
        MMA_BF16(C[1][1], a1, bf[2], bf[3]);                                  \
    }                                                                         \
} while (0)

__global__ void __launch_bounds__(NTHR, 1)
lstm_seq2seq_kernel(const float* __restrict__ inputs,
                    const float* __restrict__ eWih, const float* __restrict__ eWhh,
                    const float* __restrict__ ebih, const float* __restrict__ ebhh,
                    const float* __restrict__ dWih, const float* __restrict__ dWhh,
                    const float* __restrict__ dbih, const float* __restrict__ dbhh,
                    const float* __restrict__ linW, const float* __restrict__ linb,
                    float* __restrict__ out) {
    extern __shared__ char smraw[];
    __nv_bfloat16* W_s = (__nv_bfloat16*)smraw;        // 128 x 520 bf16
    __nv_bfloat16* A_s = W_s + NC * PITCH;             // 32 x 520 bf16
    float* G_s    = (float*)(A_s + BTILE * PITCH);     // 32 x 132 f32
    float* bias_s = G_s + BTILE * GS;                  // 128
    float* wih_s  = bias_s + NC;                       // 128
    float* x_s    = wih_s + NC;                        // 32

    const int tid    = threadIdx.x;
    const int bx     = blockIdx.x;
    const int bg     = bx & 7;             // 8 batch groups of 16 CTAs
    const int b_base = bg * BTILE;
    const int htile  = bx >> 3;            // 16 hidden tiles
    const int h_base = htile * HTILE;
    const int lane   = tid & 31;
    const int warp   = tid >> 5;           // warp tile: 32(m) x 16(n), n = warp*16
    const int jj     = tid & 31;           // hidden-within-tile
    const int bq     = tid >> 5;           // batch quad base

    // ldmatrix lane addresses
    const unsigned a_u32 = (unsigned)__cvta_generic_to_shared(A_s);
    const unsigned w_u32 = (unsigned)__cvta_generic_to_shared(W_s);
    const int lg = lane >> 3, lr = lane & 7;
    const unsigned aAddr0 = a_u32 + (unsigned)(((lg & 1) * 8 + lr) * PITCH + (lg >> 1) * 8) * 2u;
    const unsigned aAddr1 = aAddr0 + 16u * PITCH * 2u;
    const unsigned bAddr  = w_u32 + (unsigned)((warp * 16 + (lg >> 1) * 8 + lr) * PITCH + (lg & 1) * 8) * 2u;

    // Init: zero g_h[0], d_out, own flag
    {
        unsigned* h0 = (unsigned*)&g_h[0][0][0];
        for (int i = tid; i < 512; i += NTHR) h0[bx * 512 + i] = 0u;
        for (int i = tid; i < 512; i += NTHR) out[bx * 512 + i] = 0.0f;
        if (tid == 0) g_flags[bg][htile][0] = 0u;
    }
    load_w(eWhh, ebih, ebhh, eWih, W_s, bias_s, wih_s, h_base, tid);

    const float lw  = linW[h_base + jj];
    const float lb0 = linb[0];
    float creg[4];
    #pragma unroll
    for (int i = 0; i < 4; ++i) creg[i] = 0.0f;

    gridbar();   // flags reset + h/out zero + W_s visible

    for (int s = 0; s < NSTEPS; ++s) {
        const int  cur = s & 1;
        const int  nxt = cur ^ 1;
        const bool dec = (s >= SEQ);

        if (s == SEQ) {                    // switch to decoder weights
            __syncthreads();
            load_w(dWhh, dbih, dbhh, dWih, W_s, bias_s, wih_s, h_base, tid);
            __syncthreads();
        }

        const __nv_bfloat16* hsrc = &g_h[cur][0][0];

        float C[2][2][4];
        #pragma unroll
        for (int t = 0; t < 2; ++t)
            #pragma unroll
            for (int u = 0; u < 2; ++u)
                #pragma unroll
                for (int r = 0; r < 4; ++r) C[t][u][r] = 0.0f;

        GATE(0); ISSUE(0);
        GATE(1); ISSUE(1);
        asm volatile("cp.async.wait_group 1;");
        __syncthreads();
        COMP(0);
        GATE(2); ISSUE(2);
        asm volatile("cp.async.wait_group 1;");
        __syncthreads();
        COMP(1);
        GATE(3); ISSUE(3);
        asm volatile("cp.async.wait_group 1;");
        __syncthreads();
        COMP(2);
        asm volatile("cp.async.wait_group 0;");
        __syncthreads();
        COMP(3);

        // x feedback (all 16 producer flags >= s observed by the 4 gates)
        if (tid < BTILE) {
            float xv;
            if (!dec)          xv = inputs[(b_base + tid) * SEQ + s];
            else if (s == SEQ) xv = inputs[(b_base + tid) * SEQ + (SEQ - 1)];
            else               xv = __ldcg(&out[(b_base + tid) * TLEN + (s - SEQ - 1)]);
            x_s[tid] = xv;
        }

        // C frags -> gates SMEM
        #pragma unroll
        for (int t = 0; t < 2; ++t) {
            const int r = t * 16 + (lane >> 2);
            #pragma unroll
            for (int u = 0; u < 2; ++u) {
                const int cc = warp * 16 + u * 8 + (lane & 3) * 2;
                *(float2*)&G_s[r * GS + cc]       = make_float2(C[t][u][0], C[t][u][1]);
                *(float2*)&G_s[(r + 8) * GS + cc] = make_float2(C[t][u][2], C[t][u][3]);
            }
        }
        __syncthreads();

        // Epilogue: 4 cells/thread, cell (b, jj); c in registers
        #pragma unroll
        for (int ci = 0; ci < 4; ++ci) {
            const int   b  = bq + ci * 8;
            const float xv = x_s[b];
            const float* gr = G_s + b * GS;
            const float gi = gr[jj]      + bias_s[jj]      + xv * wih_s[jj];
            const float gf = gr[32 + jj] + bias_s[32 + jj] + xv * wih_s[32 + jj];
            const float gg = gr[64 + jj] + bias_s[64 + jj] + xv * wih_s[64 + jj];
            const float go = gr[96 + jj] + bias_s[96 + jj] + xv * wih_s[96 + jj];
            const float cn = sigm(gf) * creg[ci] + sigm(gi) * tanh_fast(gg);
            creg[ci] = cn;
            const float h = sigm(go) * tanh_fast(cn);
            g_h[nxt][b_base + b][h_base + jj] = __float2bfloat16_rn(h);
            if (dec) {
                float p = h * lw;
                #pragma unroll
                for (int off = 16; off; off >>= 1)
                    p += __shfl_xor_sync(0xffffffffu, p, off);
                if (lane == 0) {
                    if (htile == 0) p += lb0;
                    atomicAdd(&out[(b_base + b) * TLEN + (s - SEQ)], p);
                }
            }
        }

        // Publish: all threads' h stores (and atomics) done -> release flag
        __syncthreads();
        if (tid == 0)
            asm volatile("st.release.gpu.global.u32 [%0], %1;"
                         :: "l"(&g_flags[bg][htile][0]), "r"((unsigned)(s + 1)) : "memory");
    }
}

extern "C" void kernel_launch(void* const* d_in, const int* in_sizes, int n_in,
                              void* d_out, int out_size) {
    const float* inputs = (const float*)d_in[0];
    const float* eWih   = (const float*)d_in[1];
    const float* eWhh   = (const float*)d_in[2];
    const float* ebih   = (const float*)d_in[3];
    const float* ebhh   = (const float*)d_in[4];
    const float* dWih   = (const float*)d_in[5];
    const float* dWhh   = (const float*)d_in[6];
    const float* dbih   = (const float*)d_in[7];
    const float* dbhh   = (const float*)d_in[8];
    const float* linW   = (const float*)d_in[9];
    const float* linb   = (const float*)d_in[10];
    float* out = (float*)d_out;

    const int smem = (NC * PITCH + BTILE * PITCH) * 2                 // bf16 W + A
                   + (BTILE * GS + 2 * NC + BTILE) * 4;               // f32 G + bias/wih/x
    cudaFuncSetAttribute(lstm_seq2seq_kernel,
                         cudaFuncAttributeMaxDynamicSharedMemorySize, smem);
    lstm_seq2seq_kernel<<<NBLK, NTHR, smem>>>(inputs, eWih, eWhh, ebih, ebhh,
                                              dWih, dWhh, dbih, dbhh, linW, linb, out);
}

// round 14
// speedup vs baseline: 1.6672x; 1.2851x over previous
#include <cuda_runtime.h>
#include <cuda_bf16.h>
#include <cstdint>

#define NBLK   128
#define NTHR   256
#define SEQ    1024
#define TLEN   256
#define HID    512
#define NSTEPS (SEQ + TLEN)
#define NGRP   8       // batch groups
#define NHT    16      // hidden tiles per group
#define BTILE  32      // batches per CTA
#define HTILE  32      // hidden units per CTA
#define NC     128     // gate columns per CTA (4 gates x 32 hidden)
#define PITCH  520     // bf16 elems per SMEM row: 1040B -> LDSM conflict-free
#define GS     132     // gates_s row stride (floats)

__device__ unsigned g_bar_count;
__device__ unsigned g_bar_gen;
__device__ unsigned g_flags[NGRP][NHT][32];  // [group][htile][128B pad]
__device__ __nv_bfloat16 g_h[2][256][HID];   // ping-pong hidden state (bf16)

__device__ __forceinline__ float tanh_fast(float x) {
    float y;
    asm("tanh.approx.f32 %0, %1;" : "=f"(y) : "f"(x));
    return y;
}
__device__ __forceinline__ float sigm(float x) {
    return fmaf(tanh_fast(0.5f * x), 0.5f, 0.5f);
}

// One-time device-wide barrier (init only). 128 CTAs, 1/SM => co-resident.
__device__ __forceinline__ void gridbar() {
    __syncthreads();
    if (threadIdx.x == 0) {
        unsigned target = *(volatile unsigned*)&g_bar_gen;
        unsigned arr;
        asm volatile("atom.acq_rel.gpu.global.add.u32 %0, [%1], 1;"
                     : "=r"(arr) : "l"(&g_bar_count) : "memory");
        if (arr == NBLK - 1) {
            asm volatile("st.relaxed.gpu.global.u32 [%0], %1;"
                         :: "l"(&g_bar_count), "r"(0u) : "memory");
            asm volatile("red.release.gpu.global.add.u32 [%0], %1;"
                         :: "l"(&g_bar_gen), "r"(1u) : "memory");
        } else {
            unsigned g;
            do {
                __nanosleep(20);
                asm volatile("ld.acquire.gpu.global.u32 %0, [%1];"
                             : "=r"(g) : "l"(&g_bar_gen) : "memory");
            } while (g == target);
        }
    }
    __syncthreads();
}

__device__ __forceinline__ void load_w(const float* __restrict__ Whh,
                                       const float* __restrict__ bih,
                                       const float* __restrict__ bhh,
                                       const float* __restrict__ Wih,
                                       __nv_bfloat16* W_s, float* bias_s, float* wih_s,
                                       int h_base, int tid) {
    // SMEM gate-col n = g*32 + jj  <->  global gate row g*512 + h_base + jj
    for (int idx = tid; idx < NC * HID; idx += NTHR) {
        int n = idx >> 9;
        int k = idx & (HID - 1);
        int grow = (n >> 5) * HID + h_base + (n & 31);
        W_s[n * PITCH + k] = __float2bfloat16_rn(Whh[grow * HID + k]);
    }
    if (tid < NC) {
        int grow = (tid >> 5) * HID + h_base + (tid & 31);
        bias_s[tid] = bih[grow] + bhh[grow];
        wih_s[tid]  = Wih[grow];
    }
}

#define LDSM_X4(R, addr)                                                      \
    asm volatile("ldmatrix.sync.aligned.m8n8.x4.shared.b16 {%0,%1,%2,%3}, [%4];" \
                 : "=r"((R)[0]), "=r"((R)[1]), "=r"((R)[2]), "=r"((R)[3])     \
                 : "r"(addr))

#define MMA_BF16(C, A, B0, B1)                                                \
    asm volatile(                                                             \
        "mma.sync.aligned.m16n8k16.row.col.f32.bf16.bf16.f32 "                \
        "{%0,%1,%2,%3}, {%4,%5,%6,%7}, {%8,%9}, {%0,%1,%2,%3};"               \
        : "+f"((C)[0]), "+f"((C)[1]), "+f"((C)[2]), "+f"((C)[3])              \
        : "r"((A)[0]), "r"((A)[1]), "r"((A)[2]), "r"((A)[3]), "r"(B0), "r"(B1))

// Parallel gate: 16 lanes poll all 16 producer flags at once, tight spin.
// Each warp gates itself -> no inter-warp barrier needed before cp.async.
#define GATE_ALL() do {                                                       \
    if (lane < NHT) {                                                         \
        const unsigned* fp = &g_flags[bg][lane][0];                           \
        unsigned v;                                                           \
        do {                                                                  \
            asm volatile("ld.acquire.gpu.global.u32 %0, [%1];"                \
                         : "=r"(v) : "l"(fp) : "memory");                     \
        } while ((int)v < s);                                                 \
    }                                                                         \
    __syncwarp();                                                             \
} while (0)

// Issue chunk CH loads: 32 rows x 128 bf16 cols = 8KB = 512 x 16B, 2 per thread.
#define ISSUE(CH) do {                                                        \
    _Pragma("unroll")                                                         \
    for (int o = 0; o < 2; ++o) {                                             \
        int idx = o * 256 + tid;                                              \
        int row = idx >> 4;                                                   \
        int k   = (CH) * 128 + (idx & 15) * 8;                                \
        const __nv_bfloat16* gp = hsrc + (b_base + row) * HID + k;            \
        unsigned sdst = a_u32 + (unsigned)(row * PITCH + k) * 2u;             \
        asm volatile("cp.async.cg.shared.global [%0], [%1], 16;"              \
                     :: "r"(sdst), "l"(gp));                                  \
    }                                                                         \
    asm volatile("cp.async.commit_group;");                                   \
} while (0)

// Compute chunk CH: A and B frags via LDSM (W resident in SMEM).
#define COMP(CH) do {                                                         \
    _Pragma("unroll")                                                         \
    for (int ki = 0; ki < 8; ++ki) {                                          \
        const unsigned kkb = (unsigned)((CH) * 128 + ki * 16) * 2u;           \
        unsigned a0[4], a1[4], bf[4];                                         \
        LDSM_X4(a0, aAddr0 + kkb);                                            \
        LDSM_X4(a1, aAddr1 + kkb);                                            \
        LDSM_X4(bf, bAddr + kkb);                                             \
        MMA_BF16(C[0][0], a0, bf[0], bf[1]);                                  \
        MMA_BF16(C[0][1], a0, bf[2], bf[3]);                                  \
        MMA_BF16(C[1][0], a1, bf[0], bf[1]);                                  \
        MMA_BF16(C[1][1], a1, bf[2], bf[3]);                                  \
    }                                                                         \
} while (0)

__global__ void __launch_bounds__(NTHR, 1)
lstm_seq2seq_kernel(const float* __restrict__ inputs,
                    const float* __restrict__ eWih, const float* __restrict__ eWhh,
                    const float* __restrict__ ebih, const float* __restrict__ ebhh,
                    const float* __restrict__ dWih, const float* __restrict__ dWhh,
                    const float* __restrict__ dbih, const float* __restrict__ dbhh,
                    const float* __restrict__ linW, const float* __restrict__ linb,
                    float* __restrict__ out) {
    extern __shared__ char smraw[];
    __nv_bfloat16* W_s = (__nv_bfloat16*)smraw;        // 128 x 520 bf16
    __nv_bfloat16* A_s = W_s + NC * PITCH;             // 32 x 520 bf16
    float* G_s    = (float*)(A_s + BTILE * PITCH);     // 32 x 132 f32
    float* bias_s = G_s + BTILE * GS;                  // 128
    float* wih_s  = bias_s + NC;                       // 128
    float* x_s    = wih_s + NC;                        // 32

    const int tid    = threadIdx.x;
    const int bx     = blockIdx.x;
    const int bg     = bx & 7;             // 8 batch groups of 16 CTAs
    const int b_base = bg * BTILE;
    const int htile  = bx >> 3;            // 16 hidden tiles
    const int h_base = htile * HTILE;
    const int lane   = tid & 31;
    const int warp   = tid >> 5;           // warp tile: 32(m) x 16(n), n = warp*16
    const int jj     = tid & 31;           // hidden-within-tile
    const int bq     = tid >> 5;           // batch quad base

    // ldmatrix lane addresses
    const unsigned a_u32 = (unsigned)__cvta_generic_to_shared(A_s);
    const unsigned w_u32 = (unsigned)__cvta_generic_to_shared(W_s);
    const int lg = lane >> 3, lr = lane & 7;
    const unsigned aAddr0 = a_u32 + (unsigned)(((lg & 1) * 8 + lr) * PITCH + (lg >> 1) * 8) * 2u;
    const unsigned aAddr1 = aAddr0 + 16u * PITCH * 2u;
    const unsigned bAddr  = w_u32 + (unsigned)((warp * 16 + (lg >> 1) * 8 + lr) * PITCH + (lg & 1) * 8) * 2u;

    // Init: zero g_h[0], d_out, own flag
    {
        unsigned* h0 = (unsigned*)&g_h[0][0][0];
        for (int i = tid; i < 512; i += NTHR) h0[bx * 512 + i] = 0u;
        for (int i = tid; i < 512; i += NTHR) out[bx * 512 + i] = 0.0f;
        if (tid == 0) g_flags[bg][htile][0] = 0u;
    }
    load_w(eWhh, ebih, ebhh, eWih, W_s, bias_s, wih_s, h_base, tid);

    const float lw  = linW[h_base + jj];
    const float lb0 = linb[0];
    float creg[4];
    #pragma unroll
    for (int i = 0; i < 4; ++i) creg[i] = 0.0f;

    gridbar();   // flags reset + h/out zero + W_s visible

    for (int s = 0; s < NSTEPS; ++s) {
        const int  cur = s & 1;
        const int  nxt = cur ^ 1;
        const bool dec = (s >= SEQ);

        if (s == SEQ) {                    // switch to decoder weights
            __syncthreads();
            load_w(dWhh, dbih, dbhh, dWih, W_s, bias_s, wih_s, h_base, tid);
            __syncthreads();
        }

        const __nv_bfloat16* hsrc = &g_h[cur][0][0];

        float C[2][2][4];
        #pragma unroll
        for (int t = 0; t < 2; ++t)
            #pragma unroll
            for (int u = 0; u < 2; ++u)
                #pragma unroll
                for (int r = 0; r < 4; ++r) C[t][u][r] = 0.0f;

        // One parallel gate for all 16 producers, then issue everything.
        GATE_ALL();
        ISSUE(0); ISSUE(1); ISSUE(2); ISSUE(3);

        // x feedback in the load shadow (gated by GATE_ALL)
        float xv = 0.0f;
        if (tid < BTILE) {
            if (!dec)          xv = inputs[(b_base + tid) * SEQ + s];
            else if (s == SEQ) xv = inputs[(b_base + tid) * SEQ + (SEQ - 1)];
            else               xv = __ldcg(&out[(b_base + tid) * TLEN + (s - SEQ - 1)]);
        }

        asm volatile("cp.async.wait_group 3;");
        __syncthreads();                   // also: all warps entered step s -> x_s safe
        if (tid < BTILE) x_s[tid] = xv;
        COMP(0);
        asm volatile("cp.async.wait_group 2;");
        __syncthreads();
        COMP(1);
        asm volatile("cp.async.wait_group 1;");
        __syncthreads();
        COMP(2);
        asm volatile("cp.async.wait_group 0;");
        __syncthreads();
        COMP(3);

        // C frags -> gates SMEM
        #pragma unroll
        for (int t = 0; t < 2; ++t) {
            const int r = t * 16 + (lane >> 2);
            #pragma unroll
            for (int u = 0; u < 2; ++u) {
                const int cc = warp * 16 + u * 8 + (lane & 3) * 2;
                *(float2*)&G_s[r * GS + cc]       = make_float2(C[t][u][0], C[t][u][1]);
                *(float2*)&G_s[(r + 8) * GS + cc] = make_float2(C[t][u][2], C[t][u][3]);
            }
        }
        __syncthreads();

        // Epilogue: 4 cells/thread, cell (b, jj); c in registers
        #pragma unroll
        for (int ci = 0; ci < 4; ++ci) {
            const int   b  = bq + ci * 8;
            const float xv2 = x_s[b];
            const float* gr = G_s + b * GS;
            const float gi = gr[jj]      + bias_s[jj]      + xv2 * wih_s[jj];
            const float gf = gr[32 + jj] + bias_s[32 + jj] + xv2 * wih_s[32 + jj];
            const float gg = gr[64 + jj] + bias_s[64 + jj] + xv2 * wih_s[64 + jj];
            const float go = gr[96 + jj] + bias_s[96 + jj] + xv2 * wih_s[96 + jj];
            const float cn = sigm(gf) * creg[ci] + sigm(gi) * tanh_fast(gg);
            creg[ci] = cn;
            const float h = sigm(go) * tanh_fast(cn);
            g_h[nxt][b_base + b][h_base + jj] = __float2bfloat16_rn(h);
            if (dec) {
                float p = h * lw;
                #pragma unroll
                for (int off = 16; off; off >>= 1)
                    p += __shfl_xor_sync(0xffffffffu, p, off);
                if (lane == 0) {
                    if (htile == 0) p += lb0;
                    atomicAdd(&out[(b_base + b) * TLEN + (s - SEQ)], p);
                }
            }
        }

        // Publish: all threads' h stores (and atomics) done -> release flag
        __syncthreads();
        if (tid == 0)
            asm volatile("st.release.gpu.global.u32 [%0], %1;"
                         :: "l"(&g_flags[bg][htile][0]), "r"((unsigned)(s + 1)) : "memory");
    }
}

extern "C" void kernel_launch(void* const* d_in, const int* in_sizes, int n_in,
                              void* d_out, int out_size) {
    const float* inputs = (const float*)d_in[0];
    const float* eWih   = (const float*)d_in[1];
    const float* eWhh   = (const float*)d_in[2];
    const float* ebih   = (const float*)d_in[3];
    const float* ebhh   = (const float*)d_in[4];
    const float* dWih   = (const float*)d_in[5];
    const float* dWhh   = (const float*)d_in[6];
    const float* dbih   = (const float*)d_in[7];
    const float* dbhh   = (const float*)d_in[8];
    const float* linW   = (const float*)d_in[9];
    const float* linb   = (const float*)d_in[10];
    float* out = (float*)d_out;

    const int smem = (NC * PITCH + BTILE * PITCH) * 2                 // bf16 W + A
                   + (BTILE * GS + 2 * NC + BTILE) * 4;               // f32 G + bias/wih/x
    cudaFuncSetAttribute(lstm_seq2seq_kernel,
                         cudaFuncAttributeMaxDynamicSharedMemorySize, smem);
    lstm_seq2seq_kernel<<<NBLK, NTHR, smem>>>(inputs, eWih, eWhh, ebih, ebhh,
                                              dWih, dWhh, dbih, dbhh, linW, linb, out);
}

// round 16
// speedup vs baseline: 1.7049x; 1.0226x over previous
#include <cuda_runtime.h>
#include <cuda_bf16.h>
#include <cstdint>

#define NBLK   128
#define NTHR   256
#define SEQ    1024
#define TLEN   256
#define HID    512
#define NSTEPS (SEQ + TLEN)
#define NGRP   8       // batch groups
#define NHT    16      // hidden tiles per group
#define BTILE  32      // batches per CTA
#define HTILE  32      // hidden units per CTA
#define NC     128     // gate columns per CTA (4 gates x 32 hidden)
#define PITCH  520     // bf16 elems per SMEM row: 1040B -> LDSM conflict-free

__device__ unsigned g_bar_count;
__device__ unsigned g_bar_gen;
__device__ unsigned g_flags[NGRP][NHT][32];  // [group][htile][128B pad]
__device__ __nv_bfloat16 g_h[2][256][HID];   // ping-pong hidden state (bf16)

__device__ __forceinline__ float tanh_fast(float x) {
    float y;
    asm("tanh.approx.f32 %0, %1;" : "=f"(y) : "f"(x));
    return y;
}
__device__ __forceinline__ float sigm(float x) {
    return fmaf(tanh_fast(0.5f * x), 0.5f, 0.5f);
}

// One-time device-wide barrier (init only). 128 CTAs, 1/SM => co-resident.
__device__ __forceinline__ void gridbar() {
    __syncthreads();
    if (threadIdx.x == 0) {
        unsigned target = *(volatile unsigned*)&g_bar_gen;
        unsigned arr;
        asm volatile("atom.acq_rel.gpu.global.add.u32 %0, [%1], 1;"
                     : "=r"(arr) : "l"(&g_bar_count) : "memory");
        if (arr == NBLK - 1) {
            asm volatile("st.relaxed.gpu.global.u32 [%0], %1;"
                         :: "l"(&g_bar_count), "r"(0u) : "memory");
            asm volatile("red.release.gpu.global.add.u32 [%0], %1;"
                         :: "l"(&g_bar_gen), "r"(1u) : "memory");
        } else {
            unsigned g;
            do {
                __nanosleep(20);
                asm volatile("ld.acquire.gpu.global.u32 %0, [%1];"
                             : "=r"(g) : "l"(&g_bar_gen) : "memory");
            } while (g == target);
        }
    }
    __syncthreads();
}

// Gate-column remap: SMEM col n (0..127) <-> (hidden j, gate g):
//   w = n>>4, c = n&15, q = (c&7)>>1, g = ((c>>3)<<1) | (c&1), j = w*4 + q
// so that MMA fragments hand each thread all 4 gates of one hidden unit.
__device__ __forceinline__ void load_w(const float* __restrict__ Whh,
                                       __nv_bfloat16* W_s, int h_base, int tid) {
    for (int idx = tid; idx < NC * HID; idx += NTHR) {
        int n = idx >> 9;
        int k = idx & (HID - 1);
        int w = n >> 4, c = n & 15;
        int q = (c & 7) >> 1;
        int g = ((c >> 3) << 1) | (c & 1);
        int grow = g * HID + h_base + (w << 2) + q;
        W_s[n * PITCH + k] = __float2bfloat16_rn(Whh[grow * HID + k]);
    }
}

#define LDSM_X4(R, addr)                                                      \
    asm volatile("ldmatrix.sync.aligned.m8n8.x4.shared.b16 {%0,%1,%2,%3}, [%4];" \
                 : "=r"((R)[0]), "=r"((R)[1]), "=r"((R)[2]), "=r"((R)[3])     \
                 : "r"(addr))

#define MMA_BF16(C, A, B0, B1)                                                \
    asm volatile(                                                             \
        "mma.sync.aligned.m16n8k16.row.col.f32.bf16.bf16.f32 "                \
        "{%0,%1,%2,%3}, {%4,%5,%6,%7}, {%8,%9}, {%0,%1,%2,%3};"               \
        : "+f"((C)[0]), "+f"((C)[1]), "+f"((C)[2]), "+f"((C)[3])              \
        : "r"((A)[0]), "r"((A)[1]), "r"((A)[2]), "r"((A)[3]), "r"(B0), "r"(B1))

// Parallel gate: 16 lanes poll all 16 producer flags at once, tight spin.
#define GATE_ALL() do {                                                       \
    if (lane < NHT) {                                                         \
        const unsigned* fp = &g_flags[bg][lane][0];                           \
        unsigned v;                                                           \
        do {                                                                  \
            asm volatile("ld.acquire.gpu.global.u32 %0, [%1];"                \
                         : "=r"(v) : "l"(fp) : "memory");                     \
        } while ((int)v < s);                                                 \
    }                                                                         \
    __syncwarp();                                                             \
} while (0)

// Issue chunk CH loads: 32 rows x 128 bf16 cols = 8KB = 512 x 16B, 2 per thread.
#define ISSUE(CH) do {                                                        \
    _Pragma("unroll")                                                         \
    for (int o = 0; o < 2; ++o) {                                             \
        int idx = o * 256 + tid;                                              \
        int row = idx >> 4;                                                   \
        int k   = (CH) * 128 + (idx & 15) * 8;                                \
        const __nv_bfloat16* gp = hsrc + (b_base + row) * HID + k;            \
        unsigned sdst = a_u32 + (unsigned)(row * PITCH + k) * 2u;             \
        asm volatile("cp.async.cg.shared.global [%0], [%1], 16;"              \
                     :: "r"(sdst), "l"(gp));                                  \
    }                                                                         \
    asm volatile("cp.async.commit_group;");                                   \
} while (0)

// Compute chunk CH: A and B frags via LDSM (W resident in SMEM).
#define COMP(CH) do {                                                         \
    _Pragma("unroll")                                                         \
    for (int ki = 0; ki < 8; ++ki) {                                          \
        const unsigned kkb = (unsigned)((CH) * 128 + ki * 16) * 2u;           \
        unsigned a0[4], a1[4], bf[4];                                         \
        LDSM_X4(a0, aAddr0 + kkb);                                            \
        LDSM_X4(a1, aAddr1 + kkb);                                            \
        LDSM_X4(bf, bAddr + kkb);                                             \
        MMA_BF16(C[0][0], a0, bf[0], bf[1]);                                  \
        MMA_BF16(C[0][1], a0, bf[2], bf[3]);                                  \
        MMA_BF16(C[1][0], a1, bf[0], bf[1]);                                  \
        MMA_BF16(C[1][1], a1, bf[2], bf[3]);                                  \
    }                                                                         \
} while (0)

__global__ void __launch_bounds__(NTHR, 1)
lstm_seq2seq_kernel(const float* __restrict__ inputs,
                    const float* __restrict__ eWih, const float* __restrict__ eWhh,
                    const float* __restrict__ ebih, const float* __restrict__ ebhh,
                    const float* __restrict__ dWih, const float* __restrict__ dWhh,
                    const float* __restrict__ dbih, const float* __restrict__ dbhh,
                    const float* __restrict__ linW, const float* __restrict__ linb,
                    float* __restrict__ out) {
    extern __shared__ char smraw[];
    __nv_bfloat16* W_s = (__nv_bfloat16*)smraw;        // 128 x 520 bf16
    __nv_bfloat16* A_s = W_s + NC * PITCH;             // 32 x 520 bf16
    float* part   = (float*)(A_s + BTILE * PITCH);     // 8 x 32 f32 (decoder partials)
    float* x_s    = part + 8 * 32;                     // 32

    const int tid    = threadIdx.x;
    const int bx     = blockIdx.x;
    const int bg     = bx & 7;             // 8 batch groups of 16 CTAs
    const int b_base = bg * BTILE;
    const int htile  = bx >> 3;            // 16 hidden tiles
    const int h_base = htile * HTILE;
    const int lane   = tid & 31;
    const int warp   = tid >> 5;           // warp tile: 32(m) x 16(n)
    const int j      = (warp << 2) + (lane & 3);   // hidden unit owned by this thread
    const int hj     = h_base + j;

    // ldmatrix lane addresses
    const unsigned a_u32 = (unsigned)__cvta_generic_to_shared(A_s);
    const unsigned w_u32 = (unsigned)__cvta_generic_to_shared(W_s);
    const int lg = lane >> 3, lr = lane & 7;
    const unsigned aAddr0 = a_u32 + (unsigned)(((lg & 1) * 8 + lr) * PITCH + (lg >> 1) * 8) * 2u;
    const unsigned aAddr1 = aAddr0 + 16u * PITCH * 2u;
    const unsigned bAddr  = w_u32 + (unsigned)((warp * 16 + (lg >> 1) * 8 + lr) * PITCH + (lg & 1) * 8) * 2u;

    // Init: zero g_h[0], d_out, own flag
    {
        unsigned* h0 = (unsigned*)&g_h[0][0][0];
        for (int i = tid; i < 512; i += NTHR) h0[bx * 512 + i] = 0u;
        for (int i = tid; i < 512; i += NTHR) out[bx * 512 + i] = 0.0f;
        if (tid == 0) g_flags[bg][htile][0] = 0u;
    }
    load_w(eWhh, W_s, h_base, tid);

    // Per-thread bias/Wih registers (gates of hidden unit j)
    float bi[4], wi[4];
    #pragma unroll
    for (int g = 0; g < 4; ++g) {
        bi[g] = ebih[g * HID + hj] + ebhh[g * HID + hj];
        wi[g] = eWih[g * HID + hj];
    }

    const float lw  = linW[hj];
    const float lb0 = linb[0];
    float creg[4];                         // cells: (t, rr) -> b = lane>>2 + t*16 + rr*8
    #pragma unroll
    for (int i = 0; i < 4; ++i) creg[i] = 0.0f;

    gridbar();   // flags reset + h/out zero + W_s visible

    for (int s = 0; s < NSTEPS; ++s) {
        const int  cur = s & 1;
        const int  nxt = cur ^ 1;
        const bool dec = (s >= SEQ);

        if (s == SEQ) {                    // switch to decoder weights
            __syncthreads();
            load_w(dWhh, W_s, h_base, tid);
            #pragma unroll
            for (int g = 0; g < 4; ++g) {
                bi[g] = dbih[g * HID + hj] + dbhh[g * HID + hj];
                wi[g] = dWih[g * HID + hj];
            }
            __syncthreads();
        }

        const __nv_bfloat16* hsrc = &g_h[cur][0][0];

        float C[2][2][4];
        #pragma unroll
        for (int t = 0; t < 2; ++t)
            #pragma unroll
            for (int u = 0; u < 2; ++u)
                #pragma unroll
                for (int r = 0; r < 4; ++r) C[t][u][r] = 0.0f;

        GATE_ALL();
        ISSUE(0); ISSUE(1); ISSUE(2); ISSUE(3);

        // x feedback in the load shadow
        float xv = 0.0f;
        if (tid < BTILE) {
            if (!dec)          xv = inputs[(b_base + tid) * SEQ + s];
            else if (s == SEQ) xv = inputs[(b_base + tid) * SEQ + (SEQ - 1)];
            else               xv = __ldcg(&out[(b_base + tid) * TLEN + (s - SEQ - 1)]);
        }

        asm volatile("cp.async.wait_group 3;");
        __syncthreads();                   // all warps in step s -> x_s safe
        if (tid < BTILE) x_s[tid] = xv;
        COMP(0);
        asm volatile("cp.async.wait_group 2;");
        __syncthreads();
        COMP(1);
        asm volatile("cp.async.wait_group 1;");
        __syncthreads();
        COMP(2);
        asm volatile("cp.async.wait_group 0;");
        __syncthreads();
        COMP(3);

        // In-register epilogue: thread owns gates i/f/g/o of unit j for 4 batches.
        float p[4];
        #pragma unroll
        for (int t = 0; t < 2; ++t) {
            #pragma unroll
            for (int rr = 0; rr < 2; ++rr) {
                const int   b   = (lane >> 2) + t * 16 + rr * 8;
                const int   ci  = t * 2 + rr;
                const float xv2 = x_s[b];
                const float gi = C[t][0][rr * 2]     + bi[0] + xv2 * wi[0];
                const float gf = C[t][0][rr * 2 + 1] + bi[1] + xv2 * wi[1];
                const float gg = C[t][1][rr * 2]     + bi[2] + xv2 * wi[2];
                const float go = C[t][1][rr * 2 + 1] + bi[3] + xv2 * wi[3];
                const float cn = sigm(gf) * creg[ci] + sigm(gi) * tanh_fast(gg);
                creg[ci] = cn;
                const float h = sigm(go) * tanh_fast(cn);
                g_h[nxt][b_base + b][h_base + j] = __float2bfloat16_rn(h);
                p[ci] = h * lw;
            }
        }

        if (dec) {
            // Reduce over j: quad shfl (4 units/warp), SMEM partials, 32 atomics.
            #pragma unroll
            for (int ci = 0; ci < 4; ++ci) {
                p[ci] += __shfl_xor_sync(0xffffffffu, p[ci], 1);
                p[ci] += __shfl_xor_sync(0xffffffffu, p[ci], 2);
            }
            if ((lane & 3) == 0) {
                #pragma unroll
                for (int ci = 0; ci < 4; ++ci) {
                    const int b = (lane >> 2) + (ci >> 1) * 16 + (ci & 1) * 8;
                    part[warp * 32 + b] = p[ci];
                }
            }
            __syncthreads();
            if (tid < 32) {
                float sum = 0.0f;
                #pragma unroll
                for (int w = 0; w < 8; ++w) sum += part[w * 32 + tid];
                if (htile == 0) sum += lb0;
                atomicAdd(&out[(b_base + tid) * TLEN + (s - SEQ)], sum);
            }
        }

        // Publish: all threads' h stores (and atomics) done -> release flag
        __syncthreads();
        if (tid == 0)
            asm volatile("st.release.gpu.global.u32 [%0], %1;"
                         :: "l"(&g_flags[bg][htile][0]), "r"((unsigned)(s + 1)) : "memory");
    }
}

extern "C" void kernel_launch(void* const* d_in, const int* in_sizes, int n_in,
                              void* d_out, int out_size) {
    const float* inputs = (const float*)d_in[0];
    const float* eWih   = (const float*)d_in[1];
    const float* eWhh   = (const float*)d_in[2];
    const float* ebih   = (const float*)d_in[3];
    const float* ebhh   = (const float*)d_in[4];
    const float* dWih   = (const float*)d_in[5];
    const float* dWhh   = (const float*)d_in[6];
    const float* dbih   = (const float*)d_in[7];
    const float* dbhh   = (const float*)d_in[8];
    const float* linW   = (const float*)d_in[9];
    const float* linb   = (const float*)d_in[10];
    float* out = (float*)d_out;

    const int smem = (NC * PITCH + BTILE * PITCH) * 2       // bf16 W + A
                   + (8 * 32 + 32) * 4;                     // f32 part + x
    cudaFuncSetAttribute(lstm_seq2seq_kernel,
                         cudaFuncAttributeMaxDynamicSharedMemorySize, smem);
    lstm_seq2seq_kernel<<<NBLK, NTHR, smem>>>(inputs, eWih, eWhh, ebih, ebhh,
                                              dWih, dWhh, dbih, dbhh, linW, linb, out);
}

// round 17
// speedup vs baseline: 1.9763x; 1.1592x over previous
#include <cuda_runtime.h>
#include <cuda_bf16.h>
#include <cstdint>

#define NBLK   128
#define NTHR   128
#define SEQ    1024
#define TLEN   256
#define HID    512
#define NSTEPS (SEQ + TLEN)
#define NGRP   8       // batch groups
#define NHT    16      // hidden tiles per group
#define BTILE  32      // batches per CTA
#define HTILE  32      // hidden units per CTA
#define NC     128     // gate columns per CTA (4 gates x 32 hidden)
#define PITCH  520     // bf16 elems per SMEM row: 1040B -> LDSM conflict-free

__device__ unsigned g_bar_count;
__device__ unsigned g_bar_gen;
__device__ unsigned g_flags[NGRP][NHT][32];  // [group][htile][128B pad]
__device__ __nv_bfloat16 g_h[2][256][HID];   // ping-pong hidden state (bf16)

__device__ __forceinline__ float tanh_fast(float x) {
    float y;
    asm("tanh.approx.f32 %0, %1;" : "=f"(y) : "f"(x));
    return y;
}
__device__ __forceinline__ float sigm(float x) {
    return fmaf(tanh_fast(0.5f * x), 0.5f, 0.5f);
}

// One-time device-wide barrier (init only). 128 CTAs, 1/SM => co-resident.
__device__ __forceinline__ void gridbar() {
    __syncthreads();
    if (threadIdx.x == 0) {
        unsigned target = *(volatile unsigned*)&g_bar_gen;
        unsigned arr;
        asm volatile("atom.acq_rel.gpu.global.add.u32 %0, [%1], 1;"
                     : "=r"(arr) : "l"(&g_bar_count) : "memory");
        if (arr == NBLK - 1) {
            asm volatile("st.relaxed.gpu.global.u32 [%0], %1;"
                         :: "l"(&g_bar_count), "r"(0u) : "memory");
            asm volatile("red.release.gpu.global.add.u32 [%0], %1;"
                         :: "l"(&g_bar_gen), "r"(1u) : "memory");
        } else {
            unsigned g;
            do {
                __nanosleep(20);
                asm volatile("ld.acquire.gpu.global.u32 %0, [%1];"
                             : "=r"(g) : "l"(&g_bar_gen) : "memory");
            } while (g == target);
        }
    }
    __syncthreads();
}

// Gate-column remap for 32-wide warp tiles: SMEM col n = w*32 + c, with
// c = g*8 + q  (g = gate 0..3, q = hidden unit 0..7 within warp slice).
// MMA fragments then hand each thread all 4 gates of units q=(lane&3)*2+{0,1}.
__device__ __forceinline__ void load_w(const float* __restrict__ Whh,
                                       __nv_bfloat16* W_s, int h_base, int tid) {
    for (int idx = tid; idx < NC * HID; idx += NTHR) {
        int n = idx >> 9;
        int k = idx & (HID - 1);
        int w = n >> 5, c = n & 31;
        int q = c & 7;
        int g = c >> 3;
        int grow = g * HID + h_base + (w << 3) + q;
        W_s[n * PITCH + k] = __float2bfloat16_rn(Whh[grow * HID + k]);
    }
}

#define LDSM_X4(R, addr)                                                      \
    asm volatile("ldmatrix.sync.aligned.m8n8.x4.shared.b16 {%0,%1,%2,%3}, [%4];" \
                 : "=r"((R)[0]), "=r"((R)[1]), "=r"((R)[2]), "=r"((R)[3])     \
                 : "r"(addr))

#define MMA_BF16(C, A, B0, B1)                                                \
    asm volatile(                                                             \
        "mma.sync.aligned.m16n8k16.row.col.f32.bf16.bf16.f32 "                \
        "{%0,%1,%2,%3}, {%4,%5,%6,%7}, {%8,%9}, {%0,%1,%2,%3};"               \
        : "+f"((C)[0]), "+f"((C)[1]), "+f"((C)[2]), "+f"((C)[3])              \
        : "r"((A)[0]), "r"((A)[1]), "r"((A)[2]), "r"((A)[3]), "r"(B0), "r"(B1))

// Parallel gate: 16 lanes poll all 16 producer flags at once, tight spin.
#define GATE_ALL() do {                                                       \
    if (lane < NHT) {                                                         \
        const unsigned* fp = &g_flags[bg][lane][0];                           \
        unsigned v;                                                           \
        do {                                                                  \
            asm volatile("ld.acquire.gpu.global.u32 %0, [%1];"                \
                         : "=r"(v) : "l"(fp) : "memory");                     \
        } while ((int)v < s);                                                 \
    }                                                                         \
    __syncwarp();                                                             \
} while (0)

// Issue chunk CH loads: 32 rows x 128 bf16 cols = 8KB = 512 x 16B, 4 per thread.
#define ISSUE(CH) do {                                                        \
    _Pragma("unroll")                                                         \
    for (int o = 0; o < 4; ++o) {                                             \
        int idx = o * 128 + tid;                                              \
        int row = idx >> 4;                                                   \
        int k   = (CH) * 128 + (idx & 15) * 8;                                \
        const __nv_bfloat16* gp = hsrc + (b_base + row) * HID + k;            \
        unsigned sdst = a_u32 + (unsigned)(row * PITCH + k) * 2u;             \
        asm volatile("cp.async.cg.shared.global [%0], [%1], 16;"              \
                     :: "r"(sdst), "l"(gp));                                  \
    }                                                                         \
    asm volatile("cp.async.commit_group;");                                   \
} while (0)

// Compute chunk CH: warp tile 32(m) x 32(n); 4 LDSM.x4 + 8 MMA per k16.
#define COMP(CH) do {                                                         \
    _Pragma("unroll")                                                         \
    for (int ki = 0; ki < 8; ++ki) {                                          \
        const unsigned kkb = (unsigned)((CH) * 128 + ki * 16) * 2u;           \
        unsigned a0[4], a1[4], b0[4], b1[4];                                  \
        LDSM_X4(a0, aAddr0 + kkb);                                            \
        LDSM_X4(a1, aAddr1 + kkb);                                            \
        LDSM_X4(b0, bAddr0 + kkb);                                            \
        LDSM_X4(b1, bAddr1 + kkb);                                            \
        MMA_BF16(C[0][0], a0, b0[0], b0[1]);                                  \
        MMA_BF16(C[0][1], a0, b0[2], b0[3]);                                  \
        MMA_BF16(C[0][2], a0, b1[0], b1[1]);                                  \
        MMA_BF16(C[0][3], a0, b1[2], b1[3]);                                  \
        MMA_BF16(C[1][0], a1, b0[0], b0[1]);                                  \
        MMA_BF16(C[1][1], a1, b0[2], b0[3]);                                  \
        MMA_BF16(C[1][2], a1, b1[0], b1[1]);                                  \
        MMA_BF16(C[1][3], a1, b1[2], b1[3]);                                  \
    }                                                                         \
} while (0)

__global__ void __launch_bounds__(NTHR, 1)
lstm_seq2seq_kernel(const float* __restrict__ inputs,
                    const float* __restrict__ eWih, const float* __restrict__ eWhh,
                    const float* __restrict__ ebih, const float* __restrict__ ebhh,
                    const float* __restrict__ dWih, const float* __restrict__ dWhh,
                    const float* __restrict__ dbih, const float* __restrict__ dbhh,
                    const float* __restrict__ linW, const float* __restrict__ linb,
                    float* __restrict__ out) {
    extern __shared__ char smraw[];
    __nv_bfloat16* W_s = (__nv_bfloat16*)smraw;        // 128 x 520 bf16
    __nv_bfloat16* A_s = W_s + NC * PITCH;             // 32 x 520 bf16
    float* part   = (float*)(A_s + BTILE * PITCH);     // 4 x 32 f32 (decoder partials)
    float* x_s    = part + 4 * 32;                     // 32

    const int tid    = threadIdx.x;
    const int bx     = blockIdx.x;
    const int bg     = bx & 7;             // 8 batch groups of 16 CTAs
    const int b_base = bg * BTILE;
    const int htile  = bx >> 3;            // 16 hidden tiles
    const int h_base = htile * HTILE;
    const int lane   = tid & 31;
    const int warp   = tid >> 5;           // 4 warps, warp tile 32(m) x 32(n)
    const int q0     = (lane & 3) * 2;     // first of 2 hidden units owned
    const int hj0    = h_base + warp * 8 + q0;

    // ldmatrix lane addresses
    const unsigned a_u32 = (unsigned)__cvta_generic_to_shared(A_s);
    const unsigned w_u32 = (unsigned)__cvta_generic_to_shared(W_s);
    const int lg = lane >> 3, lr = lane & 7;
    const unsigned aAddr0 = a_u32 + (unsigned)(((lg & 1) * 8 + lr) * PITCH + (lg >> 1) * 8) * 2u;
    const unsigned aAddr1 = aAddr0 + 16u * PITCH * 2u;
    const unsigned bAddr0 = w_u32 + (unsigned)((warp * 32 + (lg >> 1) * 8 + lr) * PITCH + (lg & 1) * 8) * 2u;
    const unsigned bAddr1 = bAddr0 + 16u * PITCH * 2u;

    // Init: zero g_h[0], d_out, own flag
    {
        unsigned* h0 = (unsigned*)&g_h[0][0][0];
        for (int i = tid; i < 512; i += NTHR) h0[bx * 512 + i] = 0u;
        for (int i = tid; i < 512; i += NTHR) out[bx * 512 + i] = 0.0f;
        if (tid == 0) g_flags[bg][htile][0] = 0u;
    }
    load_w(eWhh, W_s, h_base, tid);

    // Per-thread bias/Wih registers: 2 units x 4 gates
    float bi[2][4], wi[2][4];
    #pragma unroll
    for (int e = 0; e < 2; ++e)
        #pragma unroll
        for (int g = 0; g < 4; ++g) {
            bi[e][g] = ebih[g * HID + hj0 + e] + ebhh[g * HID + hj0 + e];
            wi[e][g] = eWih[g * HID + hj0 + e];
        }

    float lw0 = linW[hj0], lw1 = linW[hj0 + 1];
    const float lb0 = linb[0];
    float creg[8];                         // 4 batches x 2 units
    #pragma unroll
    for (int i = 0; i < 8; ++i) creg[i] = 0.0f;

    gridbar();   // flags reset + h/out zero + W_s visible

    for (int s = 0; s < NSTEPS; ++s) {
        const int  cur = s & 1;
        const int  nxt = cur ^ 1;
        const bool dec = (s >= SEQ);

        if (s == SEQ) {                    // switch to decoder weights
            __syncthreads();
            load_w(dWhh, W_s, h_base, tid);
            #pragma unroll
            for (int e = 0; e < 2; ++e)
                #pragma unroll
                for (int g = 0; g < 4; ++g) {
                    bi[e][g] = dbih[g * HID + hj0 + e] + dbhh[g * HID + hj0 + e];
                    wi[e][g] = dWih[g * HID + hj0 + e];
                }
            __syncthreads();
        }

        const __nv_bfloat16* hsrc = &g_h[cur][0][0];

        float C[2][4][4];
        #pragma unroll
        for (int t = 0; t < 2; ++t)
            #pragma unroll
            for (int u = 0; u < 4; ++u)
                #pragma unroll
                for (int r = 0; r < 4; ++r) C[t][u][r] = 0.0f;

        GATE_ALL();
        ISSUE(0); ISSUE(1); ISSUE(2); ISSUE(3);

        // x feedback in the load shadow
        float xv = 0.0f;
        if (tid < BTILE) {
            if (!dec)          xv = inputs[(b_base + tid) * SEQ + s];
            else if (s == SEQ) xv = inputs[(b_base + tid) * SEQ + (SEQ - 1)];
            else               xv = __ldcg(&out[(b_base + tid) * TLEN + (s - SEQ - 1)]);
        }

        asm volatile("cp.async.wait_group 3;");
        __syncthreads();                   // all warps in step s -> x_s safe
        if (tid < BTILE) x_s[tid] = xv;
        COMP(0);
        asm volatile("cp.async.wait_group 2;");
        __syncthreads();
        COMP(1);
        asm volatile("cp.async.wait_group 1;");
        __syncthreads();
        COMP(2);
        asm volatile("cp.async.wait_group 0;");
        __syncthreads();
        COMP(3);

        // In-register epilogue: thread owns gates i/f/g/o of 2 units for 4 batches.
        float p[4];
        #pragma unroll
        for (int t = 0; t < 2; ++t) {
            #pragma unroll
            for (int rr = 0; rr < 2; ++rr) {
                const int   ci  = t * 2 + rr;
                const int   b   = t * 16 + rr * 8 + (lane >> 2);
                const float xv2 = x_s[b];
                float hv[2];
                #pragma unroll
                for (int e = 0; e < 2; ++e) {
                    const float gi = C[t][0][rr * 2 + e] + bi[e][0] + xv2 * wi[e][0];
                    const float gf = C[t][1][rr * 2 + e] + bi[e][1] + xv2 * wi[e][1];
                    const float gg = C[t][2][rr * 2 + e] + bi[e][2] + xv2 * wi[e][2];
                    const float go = C[t][3][rr * 2 + e] + bi[e][3] + xv2 * wi[e][3];
                    const float cn = sigm(gf) * creg[ci * 2 + e] + sigm(gi) * tanh_fast(gg);
                    creg[ci * 2 + e] = cn;
                    hv[e] = sigm(go) * tanh_fast(cn);
                }
                *(__nv_bfloat162*)&g_h[nxt][b_base + b][hj0] =
                    __floats2bfloat162_rn(hv[0], hv[1]);
                p[ci] = hv[0] * lw0 + hv[1] * lw1;
            }
        }

        if (dec) {
            // Reduce over units: quad shfl (8 units/warp), SMEM partials, 32 atomics.
            #pragma unroll
            for (int ci = 0; ci < 4; ++ci) {
                p[ci] += __shfl_xor_sync(0xffffffffu, p[ci], 1);
                p[ci] += __shfl_xor_sync(0xffffffffu, p[ci], 2);
            }
            if ((lane & 3) == 0) {
                #pragma unroll
                for (int ci = 0; ci < 4; ++ci) {
                    const int b = (ci >> 1) * 16 + (ci & 1) * 8 + (lane >> 2);
                    part[warp * 32 + b] = p[ci];
                }
            }
            __syncthreads();
            if (tid < 32) {
                float sum = part[tid] + part[32 + tid] + part[64 + tid] + part[96 + tid];
                if (htile == 0) sum += lb0;
                atomicAdd(&out[(b_base + tid) * TLEN + (s - SEQ)], sum);
            }
        }

        // Publish: all threads' h stores (and atomics) done -> release flag
        __syncthreads();
        if (tid == 0)
            asm volatile("st.release.gpu.global.u32 [%0], %1;"
                         :: "l"(&g_flags[bg][htile][0]), "r"((unsigned)(s + 1)) : "memory");
    }
}

extern "C" void kernel_launch(void* const* d_in, const int* in_sizes, int n_in,
                              void* d_out, int out_size) {
    const float* inputs = (const float*)d_in[0];
    const float* eWih   = (const float*)d_in[1];
    const float* eWhh   = (const float*)d_in[2];
    const float* ebih   = (const float*)d_in[3];
    const float* ebhh   = (const float*)d_in[4];
    const float* dWih   = (const float*)d_in[5];
    const float* dWhh   = (const float*)d_in[6];
    const float* dbih   = (const float*)d_in[7];
    const float* dbhh   = (const float*)d_in[8];
    const float* linW   = (const float*)d_in[9];
    const float* linb   = (const float*)d_in[10];
    float* out = (float*)d_out;

    const int smem = (NC * PITCH + BTILE * PITCH) * 2       // bf16 W + A
                   + (4 * 32 + 32) * 4;                     // f32 part + x
    cudaFuncSetAttribute(lstm_seq2seq_kernel,
                         cudaFuncAttributeMaxDynamicSharedMemorySize, smem);
    lstm_seq2seq_kernel<<<NBLK, NTHR, smem>>>(inputs, eWih, eWhh, ebih, ebhh,
                                              dWih, dWhh, dbih, dbhh, linW, linb, out);
}